// round 6
// baseline (speedup 1.0000x reference)
#include <cuda_runtime.h>
#include <math.h>

#define B_  2
#define S_  2048
#define DM  1024
#define NH  16
#define DK  64
#define WIN 512

// Scratch (allocation-free rule: __device__ globals)
__device__ float g_q[B_*NH*S_*DK];      // [B,H,S,Dk]
__device__ float g_k[B_*NH*S_*DK];
__device__ float g_v[B_*NH*S_*DK];
__device__ float g_attn[B_*S_*DM];      // [B,S,D]

// ---------------------------------------------------------------------------
// SGEMM: 128x128 block tile, BK=16, 256 threads, 8x8 register tile
// ---------------------------------------------------------------------------
#define BM 128
#define BN 128
#define BK 16

// Kernel 1: qkv = x @ w_qkv with fused RoPE epilogue scattering into g_q/g_k/g_v
__global__ __launch_bounds__(256)
void qkv_gemm_rope(const float* __restrict__ A, const float* __restrict__ Bm) {
    const int K = DM;          // 1024
    const int N = 3 * DM;      // 3072
    __shared__ float As[BK][BM];
    __shared__ float Bs[BK][BN];

    const int tid = threadIdx.x;
    const int tx = tid & 15;          // 0..15 (col group)
    const int ty = tid >> 4;          // 0..15 (row group)
    const int m0 = blockIdx.y * BM;
    const int n0 = blockIdx.x * BN;

    float acc[8][8];
    #pragma unroll
    for (int i = 0; i < 8; i++)
        #pragma unroll
        for (int j = 0; j < 8; j++) acc[i][j] = 0.f;

    for (int kt = 0; kt < K; kt += BK) {
        // Load A tile (128 x 16), store transposed As[k][m]
        #pragma unroll
        for (int it = 0; it < 2; it++) {
            int lin = tid + it * 256;           // 0..511
            int row = lin >> 2;                 // 0..127
            int c4  = (lin & 3) << 2;           // 0,4,8,12
            float4 va = *(const float4*)(A + (size_t)(m0 + row) * K + kt + c4);
            As[c4 + 0][row] = va.x;
            As[c4 + 1][row] = va.y;
            As[c4 + 2][row] = va.z;
            As[c4 + 3][row] = va.w;
        }
        // Load B tile (16 x 128)
        #pragma unroll
        for (int it = 0; it < 2; it++) {
            int lin = tid + it * 256;
            int r   = lin >> 5;                 // 0..15
            int c4  = (lin & 31) << 2;          // 0..124
            *(float4*)(&Bs[r][c4]) =
                *(const float4*)(Bm + (size_t)(kt + r) * N + n0 + c4);
        }
        __syncthreads();

        #pragma unroll
        for (int kk = 0; kk < BK; kk++) {
            float a[8], b[8];
            *(float4*)(a)     = *(float4*)&As[kk][ty * 8];
            *(float4*)(a + 4) = *(float4*)&As[kk][ty * 8 + 4];
            *(float4*)(b)     = *(float4*)&Bs[kk][tx * 8];
            *(float4*)(b + 4) = *(float4*)&Bs[kk][tx * 8 + 4];
            #pragma unroll
            for (int i = 0; i < 8; i++)
                #pragma unroll
                for (int j = 0; j < 8; j++)
                    acc[i][j] += a[i] * b[j];
        }
        __syncthreads();
    }

    // Epilogue: scatter into q/k/v with RoPE on q,k
    const int nb    = n0 + tx * 8;          // 8 consecutive cols, 8-aligned
    const int which = nb >> 10;             // 0=q 1=k 2=v (constant per block)
    const int h     = (nb & 1023) >> 6;
    const int d0    = nb & 63;              // even, multiple of 8

    if (which == 2) {
        #pragma unroll
        for (int i = 0; i < 8; i++) {
            int m = m0 + ty * 8 + i;
            int b = m >> 11, s = m & 2047;
            float* dst = g_v + (((b * NH + h) * S_ + s) * DK + d0);
            #pragma unroll
            for (int j = 0; j < 8; j++) dst[j] = acc[i][j];
        }
    } else {
        float* base = (which == 0) ? g_q : g_k;
        float invf[4];
        #pragma unroll
        for (int p = 0; p < 4; p++) {
            float t = (float)((d0 >> 1) + p);
            invf[p] = powf(10000.0f, -t / 32.0f);
        }
        #pragma unroll
        for (int i = 0; i < 8; i++) {
            int m = m0 + ty * 8 + i;
            int b = m >> 11, s = m & 2047;
            float* dst = base + (((b * NH + h) * S_ + s) * DK + d0);
            float fs = (float)s;
            #pragma unroll
            for (int p = 0; p < 4; p++) {
                float sn, cs;
                sincosf(fs * invf[p], &sn, &cs);
                float e = acc[i][2 * p];
                float o = acc[i][2 * p + 1];
                dst[2 * p]     = e * cs - o * sn;
                dst[2 * p + 1] = o * cs + e * sn;
            }
        }
    }
}

// Kernel 3: d_out = g_attn @ w_o
__global__ __launch_bounds__(256)
void oproj_gemm(const float* __restrict__ Bm, float* __restrict__ C) {
    const int K = DM, N = DM;   // 1024, 1024
    const float* A = g_attn;
    __shared__ float As[BK][BM];
    __shared__ float Bs[BK][BN];

    const int tid = threadIdx.x;
    const int tx = tid & 15;
    const int ty = tid >> 4;
    const int m0 = blockIdx.y * BM;
    const int n0 = blockIdx.x * BN;

    float acc[8][8];
    #pragma unroll
    for (int i = 0; i < 8; i++)
        #pragma unroll
        for (int j = 0; j < 8; j++) acc[i][j] = 0.f;

    for (int kt = 0; kt < K; kt += BK) {
        #pragma unroll
        for (int it = 0; it < 2; it++) {
            int lin = tid + it * 256;
            int row = lin >> 2;
            int c4  = (lin & 3) << 2;
            float4 va = *(const float4*)(A + (size_t)(m0 + row) * K + kt + c4);
            As[c4 + 0][row] = va.x;
            As[c4 + 1][row] = va.y;
            As[c4 + 2][row] = va.z;
            As[c4 + 3][row] = va.w;
        }
        #pragma unroll
        for (int it = 0; it < 2; it++) {
            int lin = tid + it * 256;
            int r   = lin >> 5;
            int c4  = (lin & 31) << 2;
            *(float4*)(&Bs[r][c4]) =
                *(const float4*)(Bm + (size_t)(kt + r) * N + n0 + c4);
        }
        __syncthreads();

        #pragma unroll
        for (int kk = 0; kk < BK; kk++) {
            float a[8], b[8];
            *(float4*)(a)     = *(float4*)&As[kk][ty * 8];
            *(float4*)(a + 4) = *(float4*)&As[kk][ty * 8 + 4];
            *(float4*)(b)     = *(float4*)&Bs[kk][tx * 8];
            *(float4*)(b + 4) = *(float4*)&Bs[kk][tx * 8 + 4];
            #pragma unroll
            for (int i = 0; i < 8; i++)
                #pragma unroll
                for (int j = 0; j < 8; j++)
                    acc[i][j] += a[i] * b[j];
        }
        __syncthreads();
    }

    #pragma unroll
    for (int i = 0; i < 8; i++) {
        int m = m0 + ty * 8 + i;
        float* dst = C + (size_t)m * N + n0 + tx * 8;
        *(float4*)(dst)     = *(float4*)(&acc[i][0]);
        *(float4*)(dst + 4) = *(float4*)(&acc[i][4]);
    }
}

// ---------------------------------------------------------------------------
// Kernel 2: sliding-window flash attention.
// grid (S/64, H, B), 64 threads; thread t owns query i = qs + t.
// K/V chunks of 64 keys staged in smem, reused by all 64 queries.
// ---------------------------------------------------------------------------
__global__ __launch_bounds__(64)
void attn_kernel() {
    __shared__ float Ks[64][64];
    __shared__ float Vs[64][64];

    const int tid = threadIdx.x;
    const int qs  = blockIdx.x * 64;
    const int h   = blockIdx.y;
    const int b   = blockIdx.z;
    const int i   = qs + tid;

    const int   base = ((b * NH + h) * S_) * DK;
    const float* qp  = g_q + base + i * DK;
    const float* kp  = g_k + base;
    const float* vp  = g_v + base;

    float qreg[64];
    #pragma unroll
    for (int d4 = 0; d4 < 16; d4++) {
        float4 t = *(const float4*)(qp + d4 * 4);
        qreg[d4 * 4 + 0] = t.x; qreg[d4 * 4 + 1] = t.y;
        qreg[d4 * 4 + 2] = t.z; qreg[d4 * 4 + 3] = t.w;
    }

    float m = -INFINITY, l = 0.f;
    float acc[64];
    #pragma unroll
    for (int d = 0; d < 64; d++) acc[d] = 0.f;

    const float scale = 0.125f;   // 1/sqrt(64)
    const int kc_start = (qs >= WIN) ? (qs - WIN) : 0;

    for (int kc = kc_start; kc < qs + 64; kc += 64) {
        // cooperative load of 64x64 K and V chunks
        for (int t = tid; t < 1024; t += 64) {
            int row = t >> 4;
            int c4  = (t & 15) << 2;
            *(float4*)&Ks[row][c4] = *(const float4*)(kp + (kc + row) * DK + c4);
            *(float4*)&Vs[row][c4] = *(const float4*)(vp + (kc + row) * DK + c4);
        }
        __syncthreads();

        #pragma unroll 4
        for (int jj = 0; jj < 64; jj++) {
            int j = kc + jj;
            if (j <= i && j >= i - WIN) {
                float s = 0.f;
                #pragma unroll
                for (int d4 = 0; d4 < 16; d4++) {
                    float4 kk4 = *(float4*)&Ks[jj][d4 * 4];
                    s += qreg[d4*4+0]*kk4.x + qreg[d4*4+1]*kk4.y
                       + qreg[d4*4+2]*kk4.z + qreg[d4*4+3]*kk4.w;
                }
                s *= scale;
                if (s <= m) {
                    float p = __expf(s - m);
                    l += p;
                    #pragma unroll
                    for (int d4 = 0; d4 < 16; d4++) {
                        float4 vv = *(float4*)&Vs[jj][d4 * 4];
                        acc[d4*4+0] += p * vv.x;
                        acc[d4*4+1] += p * vv.y;
                        acc[d4*4+2] += p * vv.z;
                        acc[d4*4+3] += p * vv.w;
                    }
                } else {
                    float corr = __expf(m - s);
                    m = s;
                    l = l * corr + 1.f;
                    #pragma unroll
                    for (int d4 = 0; d4 < 16; d4++) {
                        float4 vv = *(float4*)&Vs[jj][d4 * 4];
                        acc[d4*4+0] = acc[d4*4+0] * corr + vv.x;
                        acc[d4*4+1] = acc[d4*4+1] * corr + vv.y;
                        acc[d4*4+2] = acc[d4*4+2] * corr + vv.z;
                        acc[d4*4+3] = acc[d4*4+3] * corr + vv.w;
                    }
                }
            }
        }
        __syncthreads();
    }

    const float inv_l = 1.f / l;
    float* op = g_attn + ((size_t)(b * S_ + i)) * DM + h * DK;
    #pragma unroll
    for (int d4 = 0; d4 < 16; d4++) {
        float4 o;
        o.x = acc[d4*4+0] * inv_l;
        o.y = acc[d4*4+1] * inv_l;
        o.z = acc[d4*4+2] * inv_l;
        o.w = acc[d4*4+3] * inv_l;
        *(float4*)(op + d4 * 4) = o;
    }
}

// ---------------------------------------------------------------------------
extern "C" void kernel_launch(void* const* d_in, const int* in_sizes, int n_in,
                              void* d_out, int out_size) {
    const float* x     = (const float*)d_in[0];   // [2,2048,1024]
    const float* w_qkv = (const float*)d_in[1];   // [1024,3072]
    const float* w_o   = (const float*)d_in[2];   // [1024,1024]
    float* out = (float*)d_out;                   // [2,2048,1024]

    // 1) QKV projection + RoPE
    {
        dim3 grid(3 * DM / BN, (B_ * S_) / BM);   // (24, 32)
        qkv_gemm_rope<<<grid, 256>>>(x, w_qkv);
    }
    // 2) Sliding-window attention
    {
        dim3 grid(S_ / 64, NH, B_);               // (32, 16, 2)
        attn_kernel<<<grid, 64>>>();
    }
    // 3) Output projection
    {
        dim3 grid(DM / BN, (B_ * S_) / BM);       // (8, 32)
        oproj_gemm<<<grid, 256>>>(w_o, out);
    }
}